// round 15
// baseline (speedup 1.0000x reference)
#include <cuda_runtime.h>

#define SDIM    4096
#define HDIM    16
#define PDIM    64
#define NDIM    64
#define LCHUNK  64
#define NCHUNK  64
#define NBH     128
#define THRESH  9.0f      // truncation ~5e-5 rel (measured) << 1e-3 budget
#define THREADS 256
#define PHALF   32        // p-columns per block
#define WIN     128       // A-scan window: 2 chunks

// Dynamic smem (floats): xs[3][64][32], bs[3][64][64], ws[WIN]
#define XS_SLOT 2048
#define BS_SLOT 4096
#define XS_OFF  0
#define BS_OFF  (3 * XS_SLOT)               // 6144
#define WS_OFF  (BS_OFF + 3 * BS_SLOT)      // 18432
#define SMEM_BYTES ((WS_OFF + WIN) * 4)     // 74240 B

__device__ __forceinline__ void ffma2(unsigned long long& d,
                                      unsigned long long a,
                                      unsigned long long b) {
    asm("fma.rn.f32x2 %0, %1, %2, %0;" : "+l"(d) : "l"(a), "l"(b));
}
__device__ __forceinline__ void fadd2(unsigned long long& d, unsigned long long a) {
    asm("add.rn.f32x2 %0, %0, %1;" : "+l"(d) : "l"(a));
}
__device__ __forceinline__ unsigned long long pack2(float lo, float hi) {
    unsigned long long r;
    asm("mov.b64 %0, {%1, %2};" : "=l"(r) : "f"(lo), "f"(hi));
    return r;
}
__device__ __forceinline__ void unpack2(unsigned long long v, float& lo, float& hi) {
    asm("mov.b64 {%0, %1}, %2;" : "=f"(lo), "=f"(hi) : "l"(v));
}
__device__ __forceinline__ void cp16(float* smem_dst, const float4* gmem_src) {
    unsigned sptr = (unsigned)__cvta_generic_to_shared(smem_dst);
    asm volatile("cp.async.cg.shared.global [%0], [%1], 16;"
                 :: "r"(sptr), "l"(gmem_src) : "memory");
}
#define CP_COMMIT() asm volatile("cp.async.commit_group;" ::: "memory")
#define CP_WAIT(n)  asm volatile("cp.async.wait_group %0;" :: "n"(n) : "memory")

union F4U2 { float4 f4; unsigned long long u2[2]; };

// Load one chunk: this block's X p-half + full B.
__device__ __forceinline__ void load_chunk(float* sm, int slot, int chunk,
                                           int b, int h, int ph, int tid,
                                           const float4* X4, const float4* B4) {
    const long tbase = (long)(b * SDIM + chunk * LCHUNK) * HDIM + h;
    float* xsl = sm + XS_OFF + slot * XS_SLOT;
    float* bsl = sm + BS_OFF + slot * BS_SLOT;
    #pragma unroll
    for (int k = 0; k < 2; k++) {            // X half: 512 float4
        const int i   = k * THREADS + tid;
        const int row = i >> 3;
        const int col = i & 7;
        cp16(xsl + row * PHALF + col * 4,
             X4 + (tbase + (long)row * HDIM) * 16 + ph * 8 + col);
    }
    #pragma unroll
    for (int k = 0; k < 4; k++) {            // B full: 1024 float4
        const int i   = k * THREADS + tid;
        const int row = i >> 4;
        const int col = i & 15;
        cp16(bsl + row * 64 + col * 4,
             B4 + (tbase + (long)row * HDIM) * 16 + col);
    }
}

// Scale X tile in place (reads exactly this thread's own cp.async data).
__device__ __forceinline__ void scale_chunk(float* sm, int slot, int wsbase,
                                            int tid) {
    const float* ws = sm + WS_OFF;
    float* xsl = sm + XS_OFF + slot * XS_SLOT;
    #pragma unroll
    for (int k = 0; k < 2; k++) {
        const int i   = k * THREADS + tid;
        const int row = i >> 3;
        const int col = i & 7;
        const float w = ws[wsbase + row];
        float4 v = *(const float4*)&xsl[row * PHALF + col * 4];
        v.x *= w; v.y *= w; v.z *= w; v.w *= w;
        *(float4*)&xsl[row * PHALF + col * 4] = v;
    }
}

// 4p x 4n register tile over this l-group's 32 rows, software-pipelined.
__device__ __forceinline__ void compute_chunk(const float* sm, int slot,
                                              int lh, int p0, int n0,
                                              unsigned long long acc[2][4]) {
    const float* xsl = sm + XS_OFF + slot * XS_SLOT + lh * 32 * PHALF + p0;
    const float* bsl = sm + BS_OFF + slot * BS_SLOT + lh * 32 * 64 + n0;
    F4U2 xa;   float4 bv;
    xa.f4 = *(const float4*)xsl;
    bv    = *(const float4*)bsl;
    #pragma unroll 8
    for (int l = 0; l < 32; l++) {
        const unsigned long long b0 = pack2(bv.x, bv.x);
        const unsigned long long b1 = pack2(bv.y, bv.y);
        const unsigned long long b2 = pack2(bv.z, bv.z);
        const unsigned long long b3 = pack2(bv.w, bv.w);
        const F4U2 xc = xa;
        if (l < 31) {
            xa.f4 = *(const float4*)(xsl + (l + 1) * PHALF);
            bv    = *(const float4*)(bsl + (l + 1) * 64);
        }
        ffma2(acc[0][0], xc.u2[0], b0);
        ffma2(acc[0][1], xc.u2[0], b1);
        ffma2(acc[0][2], xc.u2[0], b2);
        ffma2(acc[0][3], xc.u2[0], b3);
        ffma2(acc[1][0], xc.u2[1], b0);
        ffma2(acc[1][1], xc.u2[1], b1);
        ffma2(acc[1][2], xc.u2[1], b2);
        ffma2(acc[1][3], xc.u2[1], b3);
    }
}

// Scan one 128-t window (2 chunks). Fills ws[0..127], sUj[0..1]. Returns
// window total. Threads 0..127 carry data; ALL 256 threads must call.
__device__ __forceinline__ float scan_window(float a, float suffix,
                                             float* ws, float* sUj,
                                             float* warpsum,
                                             int tid, int lane, int warp) {
    float sc = a;
    #pragma unroll
    for (int d = 1; d < 32; d <<= 1) {
        float o = __shfl_up_sync(0xffffffffu, sc, d);
        if (lane >= d) sc += o;
    }
    if (warp < 4 && lane == 31) warpsum[warp] = sc;
    __syncthreads();
    if (warp == 0 && lane < 4) {
        float v = warpsum[lane];
        #pragma unroll
        for (int d = 1; d < 4; d <<= 1) {
            float o = __shfl_up_sync(0x0000000fu, v, d);
            if (lane >= d) v += o;
        }
        warpsum[lane] = v;
    }
    __syncthreads();
    const float total = warpsum[3];
    if (tid < WIN) {
        const float off = (warp > 0) ? warpsum[warp - 1] : 0.0f;
        const float u = total - (sc + off) + suffix;   // sum of A after t
        ws[tid] = __expf(u);
        if ((tid & 63) == 63) sUj[tid >> 6] = u;       // suffix after chunk
    }
    __syncthreads();
    return total;
}

__global__ void __launch_bounds__(THREADS, 2)
fused_mamba_kernel(const float* __restrict__ X,
                   const float* __restrict__ A,
                   const float* __restrict__ B,
                   float* __restrict__ out) {
    extern __shared__ float sm[];
    float* ws = sm + WS_OFF;

    __shared__ float warpsum[4];
    __shared__ float sUj[2];

    const int bh   = blockIdx.x;
    const int ph   = blockIdx.y;        // p-half (0/1) — also stagger parity
    const int b    = bh >> 4;
    const int h    = bh & 15;
    const int tid  = threadIdx.x;
    const int lane = tid & 31;
    const int warp = tid >> 5;
    const int lh   = tid >> 7;          // l-half group (0/1)
    const int r    = tid & 127;
    const int p0   = (r >> 4) << 2;     // 4 p-values within half (0..28)
    const int n0   = (r & 15) << 2;     // 4 n-values (0..60)

    const float4* X4 = (const float4*)X;
    const float4* B4 = (const float4*)B;
    const float*  Ab = A + (long)b * SDIM * HDIM + h;

    // Staggered chunk order: ph=0 does 63 then 62; ph=1 does 62 then 63.
    const int cA = ph ? 62 : 63;        // slot/wsbase derive from chunk-62
    const int cB = ph ? 63 : 62;
    const int sA = cA - 62, sB = cB - 62;

    // ---- Issue A-window loads FIRST (long-latency, uncoalesced) -----------
    const int win0 = SDIM - WIN;        // 3968: chunks 62..63
    float a_pre = (tid < WIN) ? Ab[(win0 + tid) * HDIM] : 0.0f;

    // ---- Speculative prefetch (staggered order) -----------------------------
    load_chunk(sm, sA, cA, b, h, ph, tid, X4, B4);  CP_COMMIT();
    load_chunk(sm, sB, cB, b, h, ph, tid, X4, B4);  CP_COMMIT();

    // ---- Window scan (chunks 62,63); total = suffix after chunk 61 --------
    const float total = scan_window(a_pre, 0.0f, ws, sUj, warpsum,
                                    tid, lane, warp);

    unsigned long long acc[2][4];
    #pragma unroll
    for (int i = 0; i < 2; i++)
        #pragma unroll
        for (int n = 0; n < 4; n++) acc[i][n] = 0ull;

    // ---- Single wait + single barrier for both main chunks ------------------
    CP_WAIT(0);
    scale_chunk(sm, sA, sA * 64, tid);
    scale_chunk(sm, sB, sB * 64, tid);
    __syncthreads();
    compute_chunk(sm, sA, lh, p0, n0, acc);
    compute_chunk(sm, sB, lh, p0, n0, acc);

    // ---- Earlier chunks (4% tail; always-correct generic path) -------------
    float suffix = total;
    int wbase = SDIM - 2 * WIN;         // 3840: chunks 60..61
    while (suffix > -THRESH && wbase >= 0) {
        float a2 = (tid < WIN) ? Ab[(wbase + tid) * HDIM] : 0.0f;
        const float wtot = scan_window(a2, suffix, ws, sUj, warpsum,
                                       tid, lane, warp);
        for (int jj = 1; jj >= 0; jj--) {
            if (sUj[jj] > -THRESH) {
                const int c = (wbase >> 6) + jj;
                const int slot = c % 3;
                __syncthreads();        // slot reuse vs prior compute
                load_chunk(sm, slot, c, b, h, ph, tid, X4, B4);
                CP_COMMIT(); CP_WAIT(0);
                scale_chunk(sm, slot, jj * 64, tid);
                __syncthreads();
                compute_chunk(sm, slot, lh, p0, n0, acc);
            }
        }
        suffix += wtot;
        wbase -= WIN;
    }

    // ---- Cross-group reduction (group1 -> smem, group0 adds) -----------------
    __syncthreads();
    unsigned long long* buf = (unsigned long long*)sm;   // reuse xs region (8KB)
    if (lh == 1) {
        #pragma unroll
        for (int q = 0; q < 8; q++)
            buf[q * 128 + r] = acc[q >> 2][q & 3];
    }
    __syncthreads();
    if (lh == 0) {
        #pragma unroll
        for (int q = 0; q < 8; q++)
            fadd2(acc[q >> 2][q & 3], buf[q * 128 + r]);

        // ---- Write out[bh, ph*32 + p, n] -------------------------------------
        float4* out4 = (float4*)out + (long)bh * PDIM * 16 + ph * 32 * 16;
        #pragma unroll
        for (int pi = 0; pi < 2; pi++) {
            float4 vlo, vhi;
            unpack2(acc[pi][0], vlo.x, vhi.x);
            unpack2(acc[pi][1], vlo.y, vhi.y);
            unpack2(acc[pi][2], vlo.z, vhi.z);
            unpack2(acc[pi][3], vlo.w, vhi.w);
            out4[(p0 + 2 * pi)     * 16 + (n0 >> 2)] = vlo;
            out4[(p0 + 2 * pi + 1) * 16 + (n0 >> 2)] = vhi;
        }
    }
}

// ---------------------------------------------------------------------------
extern "C" void kernel_launch(void* const* d_in, const int* in_sizes, int n_in,
                              void* d_out, int out_size) {
    const float* X = (const float*)d_in[0];
    const float* A = (const float*)d_in[1];
    const float* B = (const float*)d_in[2];
    float* out = (float*)d_out;

    cudaFuncSetAttribute(fused_mamba_kernel,
                         cudaFuncAttributeMaxDynamicSharedMemorySize,
                         SMEM_BYTES);
    dim3 grid(NBH, 2);
    fused_mamba_kernel<<<grid, THREADS, SMEM_BYTES>>>(X, A, B, out);
}